// round 5
// baseline (speedup 1.0000x reference)
#include <cuda_runtime.h>
#include <cstdint>

#define BINS 10
#define C 16
#define MAX_BLOCKS 1184   // 8 * 148 SMs
#define THREADS 256
#define WARPS_PER_BLOCK (THREADS / 32)

// Allocation-free scratch: per-block, per-bin partials + completion ticket.
__device__ float    g_part_sum[BINS * MAX_BLOCKS];
__device__ unsigned g_part_cnt[BINS * MAX_BLOCKS];
__device__ unsigned g_done = 0;   // returns to 0 every run (deterministic)

__global__ __launch_bounds__(THREADS) void ghm_fused_kernel(
    const float* __restrict__ x,
    const int* __restrict__ tgt,   // int32 targets in {0,1}
    float* __restrict__ out,
    int N)
{
    const int lane = threadIdx.x & 31;
    const int sub  = lane & 3;     // element-quad within a row
    const int grp  = lane >> 2;    // row within the 8-row group
    const int wid  = blockIdx.x * WARPS_PER_BLOCK + (threadIdx.x >> 5);
    const int nw   = gridDim.x * WARPS_PER_BLOCK;

    float    lsum[BINS];
    unsigned lcnt[BINS];
#pragma unroll
    for (int b = 0; b < BINS; b++) { lsum[b] = 0.0f; lcnt[b] = 0u; }

    // Each warp-iteration covers 16 rows: two contiguous 512B LDG.128 loads.
    for (long long base = (long long)wid * 16; base < N; base += (long long)nw * 16) {
        int row0 = (int)base + grp;
        int row1 = (int)base + 8 + grp;
        bool ok0 = row0 < N;
        bool ok1 = row1 < N;

        const float4* p = reinterpret_cast<const float4*>(x) + base * 4;
        float4 f0 = ok0 ? __ldcs(p + lane)      : make_float4(0.f, 0.f, 0.f, 0.f);
        float4 f1 = ok1 ? __ldcs(p + 32 + lane) : make_float4(0.f, 0.f, 0.f, 0.f);

        int t0 = 0, t1 = 0;
        if (sub == 0) {
            if (ok0) t0 = min(max(__ldcs(tgt + row0), 0), 1);
            if (ok1) t1 = min(max(__ldcs(tgt + row1), 0), 1);
        }

#pragma unroll
        for (int u = 0; u < 2; u++) {
            float4 f = u ? f1 : f0;
            int    t = u ? t1 : t0;
            bool  ok = u ? ok1 : ok0;

            // group-of-4 max
            float m = fmaxf(fmaxf(f.x, f.y), fmaxf(f.z, f.w));
            m = fmaxf(m, __shfl_xor_sync(0xFFFFFFFFu, m, 1));
            m = fmaxf(m, __shfl_xor_sync(0xFFFFFFFFu, m, 2));

            float e0 = __expf(f.x - m);
            float e1 = __expf(f.y - m);
            float e2 = __expf(f.z - m);
            float e3 = __expf(f.w - m);
            float s  = (e0 + e1) + (e2 + e3);
            s += __shfl_xor_sync(0xFFFFFFFFu, s, 1);
            s += __shfl_xor_sync(0xFFFFFFFFu, s, 2);

            if (sub == 0 && ok) {
                float xt = t ? f.y : f.x;
                float et = t ? e1  : e0;
                float nll = m + __logf(s) - xt;       // -log_softmax[t]
                float pt  = __fdividef(et, s);        // softmax[t]
                float g   = fabsf(pt - (float)t);

                // searchsorted(arange(11)/10, g, 'right') - 1, clipped to 9
                int bin = 0;
#pragma unroll
                for (int j = 1; j <= BINS; j++) bin += (g >= (float)j / 10.0f) ? 1 : 0;
                if (bin > BINS - 1) bin = BINS - 1;

                // constant-indexed predicated accumulate (register-resident)
#pragma unroll
                for (int b = 0; b < BINS; b++) {
                    bool hit = (bin == b);
                    lsum[b] += hit ? nll : 0.0f;
                    lcnt[b] += hit ? 1u : 0u;
                }
            }
        }
    }

    // ---- block reduction: warp shuffle -> shared atomics -> global partials ----
    __shared__ float    s_sum[BINS];
    __shared__ unsigned s_cnt[BINS];
    if (threadIdx.x < BINS) { s_sum[threadIdx.x] = 0.0f; s_cnt[threadIdx.x] = 0u; }
    __syncthreads();

#pragma unroll
    for (int b = 0; b < BINS; b++) {
        float    vs = lsum[b];
        unsigned vc = lcnt[b];
#pragma unroll
        for (int off = 16; off > 0; off >>= 1) {
            vs += __shfl_down_sync(0xFFFFFFFFu, vs, off);
            vc += __shfl_down_sync(0xFFFFFFFFu, vc, off);
        }
        if (lane == 0) {
            atomicAdd(&s_sum[b], vs);
            atomicAdd(&s_cnt[b], vc);
        }
    }
    __syncthreads();

    if (threadIdx.x < BINS) {
        g_part_sum[threadIdx.x * MAX_BLOCKS + blockIdx.x] = s_sum[threadIdx.x];
        g_part_cnt[threadIdx.x * MAX_BLOCKS + blockIdx.x] = s_cnt[threadIdx.x];
    }

    // ---- last-block final reduction (fused tail) ----
    __threadfence();
    __syncthreads();
    __shared__ bool is_last;
    if (threadIdx.x == 0) {
        unsigned prev = atomicAdd(&g_done, 1u);
        is_last = (prev == gridDim.x - 1);
    }
    __syncthreads();

    if (is_last) {
        __shared__ double term[BINS];
        int w = threadIdx.x >> 5;
        // warps 0..7 handle bins w and w+8
        for (int bin = w; bin < BINS; bin += WARPS_PER_BLOCK) {
            float    fs = 0.0f;
            unsigned fc = 0u;
            for (int blk = lane; blk < gridDim.x; blk += 32) {
                fs += g_part_sum[bin * MAX_BLOCKS + blk];
                fc += g_part_cnt[bin * MAX_BLOCKS + blk];
            }
#pragma unroll
            for (int off = 16; off > 0; off >>= 1) {
                fs += __shfl_down_sync(0xFFFFFFFFu, fs, off);
                fc += __shfl_down_sync(0xFFFFFFFFu, fc, off);
            }
            if (lane == 0) {
                double c = (double)fc;
                if (c < 1.0) c = 1.0;
                term[bin] = ((double)N / (double)BINS) / c * (double)fs;
            }
        }
        __syncthreads();
        if (threadIdx.x == 0) {
            double total = 0.0;
#pragma unroll
            for (int b = 0; b < BINS; b++) total += term[b];
            out[0] = (float)total;
            g_done = 0;   // reset for next (graph-replayed) run
        }
    }
}

extern "C" void kernel_launch(void* const* d_in, const int* in_sizes, int n_in,
                              void* d_out, int out_size)
{
    // Robust input-order detection: inputs has C=16x more elements than target.
    int i_x = 0, i_t = 1;
    if (n_in >= 2 && in_sizes[1] > in_sizes[0]) { i_x = 1; i_t = 0; }

    const float* x   = (const float*)d_in[i_x];
    const int*   tgt = (const int*)d_in[i_t];
    float*       out = (float*)d_out;

    int N = in_sizes[i_t];
    (void)out_size;

    int blocks = MAX_BLOCKS;
    long long rows_per_warp_pass = (long long)WARPS_PER_BLOCK * 16;
    long long maxb = ((long long)N + rows_per_warp_pass - 1) / rows_per_warp_pass;
    if (blocks > maxb) blocks = (int)maxb;
    if (blocks < 1) blocks = 1;

    ghm_fused_kernel<<<blocks, THREADS>>>(x, tgt, out, N);
}

// round 6
// speedup vs baseline: 1.2931x; 1.2931x over previous
#include <cuda_runtime.h>
#include <cstdint>

#define BINS 10
#define THREADS 256
#define TILE_ROWS 256
#define CHUNK_W 1032          // words per chunk plane: 256*4 + 8 pad (bank-conflict-free)
#define MAX_BLOCKS 888        // 6 blocks/SM * 148 SMs

// Allocation-free scratch: per-block, per-bin partials + completion ticket.
__device__ float    g_part_sum[BINS * MAX_BLOCKS];
__device__ unsigned g_part_cnt[BINS * MAX_BLOCKS];
__device__ unsigned g_done = 0;   // returns to 0 every run (deterministic)

__device__ __forceinline__ uint32_t smem_u32(const void* p) {
    return (uint32_t)__cvta_generic_to_shared(p);
}

__global__ __launch_bounds__(THREADS) void ghm_fused_kernel(
    const float* __restrict__ x,
    const int* __restrict__ tgt,   // int32 targets in {0,1}
    float* __restrict__ out,
    int N)
{
    // Double-buffered staging: chunk-major padded layout.
    // Row r, chunk c (c-th float4 of the row) lives at sdata[buf][c*CHUNK_W + r*4].
    __shared__ __align__(16) float sdata[2][4 * CHUNK_W];
    __shared__ int stgt[2][TILE_ROWS];

    const int tid = threadIdx.x;
    const int lane = tid & 31;
    const long long ntiles = ((long long)N + TILE_ROWS - 1) / TILE_ROWS;

    float    lsum[BINS];
    unsigned lcnt[BINS];
#pragma unroll
    for (int b = 0; b < BINS; b++) { lsum[b] = 0.0f; lcnt[b] = 0u; }

    // ---- software-pipelined tile loop ----
    long long tile = blockIdx.x;

    // prologue: async-load first tile into buffer 0
    {
        long long base_row = tile * TILE_ROWS;
        const float4* gsrc = reinterpret_cast<const float4*>(x) + base_row * 4;
#pragma unroll
        for (int r = 0; r < 4; r++) {
            int g4 = r * THREADS + tid;          // float4 index within tile
            int relrow = g4 >> 2, chunk = g4 & 3;
            if (base_row + relrow < N) {
                uint32_t sa = smem_u32(&sdata[0][chunk * CHUNK_W + relrow * 4]);
                asm volatile("cp.async.cg.shared.global [%0], [%1], 16;"
                             :: "r"(sa), "l"(gsrc + g4));
            }
        }
        if (base_row + tid < N) {
            uint32_t sa = smem_u32(&stgt[0][tid]);
            asm volatile("cp.async.ca.shared.global [%0], [%1], 4;"
                         :: "r"(sa), "l"(tgt + base_row + tid));
        }
    }
    asm volatile("cp.async.commit_group;");

    int buf = 0;
    while (true) {
        long long next = tile + gridDim.x;

        // protect buf^1 (computed last iteration) before overwriting it
        __syncthreads();

        if (next < ntiles) {
            long long base_row = next * TILE_ROWS;
            const float4* gsrc = reinterpret_cast<const float4*>(x) + base_row * 4;
#pragma unroll
            for (int r = 0; r < 4; r++) {
                int g4 = r * THREADS + tid;
                int relrow = g4 >> 2, chunk = g4 & 3;
                if (base_row + relrow < N) {
                    uint32_t sa = smem_u32(&sdata[buf ^ 1][chunk * CHUNK_W + relrow * 4]);
                    asm volatile("cp.async.cg.shared.global [%0], [%1], 16;"
                                 :: "r"(sa), "l"(gsrc + g4));
                }
            }
            if (base_row + tid < N) {
                uint32_t sa = smem_u32(&stgt[buf ^ 1][tid]);
                asm volatile("cp.async.ca.shared.global [%0], [%1], 4;"
                             :: "r"(sa), "l"(tgt + base_row + tid));
            }
        }
        asm volatile("cp.async.commit_group;");
        asm volatile("cp.async.wait_group 1;");   // current tile's group is complete
        __syncthreads();

        // ---- compute this thread's row of tile ----
        long long row = tile * TILE_ROWS + tid;
        if (row < N) {
            const float* sp = &sdata[buf][tid * 4];
            float4 f0 = *reinterpret_cast<const float4*>(sp + 0 * CHUNK_W);
            float4 f1 = *reinterpret_cast<const float4*>(sp + 1 * CHUNK_W);
            float4 f2 = *reinterpret_cast<const float4*>(sp + 2 * CHUNK_W);
            float4 f3 = *reinterpret_cast<const float4*>(sp + 3 * CHUNK_W);
            int t = min(max(stgt[buf][tid], 0), 1);

            float m01 = fmaxf(fmaxf(f0.x, f0.y), fmaxf(f0.z, f0.w));
            float m23 = fmaxf(fmaxf(f1.x, f1.y), fmaxf(f1.z, f1.w));
            float m45 = fmaxf(fmaxf(f2.x, f2.y), fmaxf(f2.z, f2.w));
            float m67 = fmaxf(fmaxf(f3.x, f3.y), fmaxf(f3.z, f3.w));
            float m = fmaxf(fmaxf(m01, m23), fmaxf(m45, m67));

            float e0 = __expf(f0.x - m);
            float e1 = __expf(f0.y - m);
            float s = e0 + e1;
            s += __expf(f0.z - m); s += __expf(f0.w - m);
            s += __expf(f1.x - m); s += __expf(f1.y - m);
            s += __expf(f1.z - m); s += __expf(f1.w - m);
            s += __expf(f2.x - m); s += __expf(f2.y - m);
            s += __expf(f2.z - m); s += __expf(f2.w - m);
            s += __expf(f3.x - m); s += __expf(f3.y - m);
            s += __expf(f3.z - m); s += __expf(f3.w - m);

            float xt = t ? f0.y : f0.x;
            float et = t ? e1   : e0;
            float nll = m + __logf(s) - xt;     // -log_softmax[t]
            float pt  = __fdividef(et, s);      // softmax[t]
            float g   = fabsf(pt - (float)t);   // gradient norm

            // bin = searchsorted(arange(11)/10, g, 'right') - 1, clipped to 9
            int bin = 0;
#pragma unroll
            for (int j = 1; j <= BINS; j++) bin += (g >= (float)j / 10.0f) ? 1 : 0;
            if (bin > BINS - 1) bin = BINS - 1;

            // register-resident predicated accumulate
#pragma unroll
            for (int b = 0; b < BINS; b++) {
                bool hit = (bin == b);
                lsum[b] += hit ? nll : 0.0f;
                lcnt[b] += hit ? 1u : 0u;
            }
        }

        buf ^= 1;
        tile = next;
        if (tile >= ntiles) break;
    }

    // ---- block reduction: warp shuffle -> shared atomics -> global partials ----
    __shared__ float    s_sum[BINS];
    __shared__ unsigned s_cnt[BINS];
    if (tid < BINS) { s_sum[tid] = 0.0f; s_cnt[tid] = 0u; }
    __syncthreads();

#pragma unroll
    for (int b = 0; b < BINS; b++) {
        float    vs = lsum[b];
        unsigned vc = lcnt[b];
#pragma unroll
        for (int off = 16; off > 0; off >>= 1) {
            vs += __shfl_down_sync(0xFFFFFFFFu, vs, off);
            vc += __shfl_down_sync(0xFFFFFFFFu, vc, off);
        }
        if (lane == 0) {
            atomicAdd(&s_sum[b], vs);
            atomicAdd(&s_cnt[b], vc);
        }
    }
    __syncthreads();

    if (tid < BINS) {
        g_part_sum[tid * MAX_BLOCKS + blockIdx.x] = s_sum[tid];
        g_part_cnt[tid * MAX_BLOCKS + blockIdx.x] = s_cnt[tid];
    }

    // ---- last-block final reduction (fused tail) ----
    __threadfence();
    __syncthreads();
    __shared__ bool is_last;
    if (tid == 0) {
        unsigned prev = atomicAdd(&g_done, 1u);
        is_last = (prev == gridDim.x - 1);
    }
    __syncthreads();

    if (is_last) {
        __shared__ double term[BINS];
        int w = tid >> 5;
        for (int bin = w; bin < BINS; bin += (THREADS / 32)) {
            float    fs = 0.0f;
            unsigned fc = 0u;
            for (int blk = lane; blk < (int)gridDim.x; blk += 32) {
                fs += g_part_sum[bin * MAX_BLOCKS + blk];
                fc += g_part_cnt[bin * MAX_BLOCKS + blk];
            }
#pragma unroll
            for (int off = 16; off > 0; off >>= 1) {
                fs += __shfl_down_sync(0xFFFFFFFFu, fs, off);
                fc += __shfl_down_sync(0xFFFFFFFFu, fc, off);
            }
            if (lane == 0) {
                double c = (double)fc;
                if (c < 1.0) c = 1.0;
                term[bin] = ((double)N / (double)BINS) / c * (double)fs;
            }
        }
        __syncthreads();
        if (tid == 0) {
            double total = 0.0;
#pragma unroll
            for (int b = 0; b < BINS; b++) total += term[b];
            out[0] = (float)total;
            g_done = 0;   // reset for next (graph-replayed) run
        }
    }
}

extern "C" void kernel_launch(void* const* d_in, const int* in_sizes, int n_in,
                              void* d_out, int out_size)
{
    // Robust input-order detection: inputs has 16x more elements than target.
    int i_x = 0, i_t = 1;
    if (n_in >= 2 && in_sizes[1] > in_sizes[0]) { i_x = 1; i_t = 0; }

    const float* x   = (const float*)d_in[i_x];
    const int*   tgt = (const int*)d_in[i_t];
    float*       out = (float*)d_out;

    int N = in_sizes[i_t];
    (void)out_size;

    long long ntiles = ((long long)N + TILE_ROWS - 1) / TILE_ROWS;
    int blocks = MAX_BLOCKS;
    if ((long long)blocks > ntiles) blocks = (int)ntiles;
    if (blocks < 1) blocks = 1;

    ghm_fused_kernel<<<blocks, THREADS>>>(x, tgt, out, N);
}

// round 7
// speedup vs baseline: 2.0451x; 1.5816x over previous
#include <cuda_runtime.h>
#include <cstdint>

#define BINS 10
#define THREADS 256
#define NWARPS 8
#define MAX_BLOCKS 592   // 4 blocks/SM * 148 SMs

// Allocation-free scratch: per-block, per-bin partials + completion ticket.
__device__ float    g_part_sum[BINS * MAX_BLOCKS];
__device__ unsigned g_part_cnt[BINS * MAX_BLOCKS];
__device__ unsigned g_done = 0;   // returns to 0 every run (deterministic)

__global__ __launch_bounds__(THREADS) void ghm_fused_kernel(
    const float* __restrict__ x,
    const int* __restrict__ tgt,   // int32 targets in {0,1}
    float* __restrict__ out,
    int N)
{
    // Warp-private transpose slices: 32 rows x 16 floats (2KB/warp).
    // XOR-swizzled: chunk j of row r lives at slot (j ^ ((r>>1)&3)).
    // Both STS.128 and LDS.128 phases are bank-conflict-free at stride 64B.
    __shared__ __align__(16) float strans[NWARPS][32 * 16];

    const int lane  = threadIdx.x & 31;
    const int warp  = threadIdx.x >> 5;
    const int gwarp = blockIdx.x * NWARPS + warp;
    const int nw    = gridDim.x * NWARPS;
    float* slice = strans[warp];

    float    lsum[BINS];
    unsigned lcnt[BINS];
#pragma unroll
    for (int b = 0; b < BINS; b++) { lsum[b] = 0.0f; lcnt[b] = 0u; }

    for (long long base = (long long)gwarp * 32; base < N; base += (long long)nw * 32) {
        const float4* gp = reinterpret_cast<const float4*>(x) + base * 4;

        // 4 fully-coalesced 512B loads (streaming; every sector used once)
        float4 f[4];
        if (base + 32 <= (long long)N) {
#pragma unroll
            for (int k = 0; k < 4; k++) f[k] = __ldcs(gp + k * 32 + lane);
        } else {
#pragma unroll
            for (int k = 0; k < 4; k++) {
                long long r = base + ((32 * k + lane) >> 2);
                f[k] = (r < N) ? __ldcs(gp + k * 32 + lane)
                               : make_float4(0.f, 0.f, 0.f, 0.f);
            }
        }

        long long myrow = base + lane;           // this thread's row (coalesced tgt)
        int t = 0;
        if (myrow < (long long)N) t = min(max(__ldcs(tgt + myrow), 0), 1);

        __syncwarp();   // prev iteration's LDS must finish before overwrite
#pragma unroll
        for (int k = 0; k < 4; k++) {
            int row  = 8 * k + (lane >> 2);
            int slot = (lane & 3) ^ ((row >> 1) & 3);
            *reinterpret_cast<float4*>(&slice[row * 16 + slot * 4]) = f[k];
        }
        __syncwarp();

        // read own row (conflict-free swizzled LDS.128 x4)
        const int s = (lane >> 1) & 3;
        float4 v0 = *reinterpret_cast<const float4*>(&slice[lane * 16 + ((0 ^ s) * 4)]);
        float4 v1 = *reinterpret_cast<const float4*>(&slice[lane * 16 + ((1 ^ s) * 4)]);
        float4 v2 = *reinterpret_cast<const float4*>(&slice[lane * 16 + ((2 ^ s) * 4)]);
        float4 v3 = *reinterpret_cast<const float4*>(&slice[lane * 16 + ((3 ^ s) * 4)]);

        if (myrow < (long long)N) {
            float m01 = fmaxf(fmaxf(v0.x, v0.y), fmaxf(v0.z, v0.w));
            float m23 = fmaxf(fmaxf(v1.x, v1.y), fmaxf(v1.z, v1.w));
            float m45 = fmaxf(fmaxf(v2.x, v2.y), fmaxf(v2.z, v2.w));
            float m67 = fmaxf(fmaxf(v3.x, v3.y), fmaxf(v3.z, v3.w));
            float m = fmaxf(fmaxf(m01, m23), fmaxf(m45, m67));

            float e0 = __expf(v0.x - m);
            float e1 = __expf(v0.y - m);
            float sum = e0 + e1;
            sum += __expf(v0.z - m); sum += __expf(v0.w - m);
            sum += __expf(v1.x - m); sum += __expf(v1.y - m);
            sum += __expf(v1.z - m); sum += __expf(v1.w - m);
            sum += __expf(v2.x - m); sum += __expf(v2.y - m);
            sum += __expf(v2.z - m); sum += __expf(v2.w - m);
            sum += __expf(v3.x - m); sum += __expf(v3.y - m);
            sum += __expf(v3.z - m); sum += __expf(v3.w - m);

            float xt = t ? v0.y : v0.x;
            float et = t ? e1   : e0;
            float nll = m + __logf(sum) - xt;       // -log_softmax[t]
            float pt  = __fdividef(et, sum);        // softmax[t]
            float g   = fabsf(pt - (float)t);       // gradient norm

            // bin = searchsorted(arange(11)/10, g, 'right') - 1, clipped to 9
            int bin = 0;
#pragma unroll
            for (int j = 1; j <= BINS; j++) bin += (g >= (float)j / 10.0f) ? 1 : 0;
            if (bin > BINS - 1) bin = BINS - 1;

            // register-resident predicated accumulate
#pragma unroll
            for (int b = 0; b < BINS; b++) {
                bool hit = (bin == b);
                lsum[b] += hit ? nll : 0.0f;
                lcnt[b] += hit ? 1u : 0u;
            }
        }
    }

    // ---- block reduction: warp shuffle -> shared atomics -> global partials ----
    __shared__ float    s_sum[BINS];
    __shared__ unsigned s_cnt[BINS];
    if (threadIdx.x < BINS) { s_sum[threadIdx.x] = 0.0f; s_cnt[threadIdx.x] = 0u; }
    __syncthreads();

#pragma unroll
    for (int b = 0; b < BINS; b++) {
        float    vs = lsum[b];
        unsigned vc = lcnt[b];
#pragma unroll
        for (int off = 16; off > 0; off >>= 1) {
            vs += __shfl_down_sync(0xFFFFFFFFu, vs, off);
            vc += __shfl_down_sync(0xFFFFFFFFu, vc, off);
        }
        if (lane == 0) {
            atomicAdd(&s_sum[b], vs);
            atomicAdd(&s_cnt[b], vc);
        }
    }
    __syncthreads();

    if (threadIdx.x < BINS) {
        g_part_sum[threadIdx.x * MAX_BLOCKS + blockIdx.x] = s_sum[threadIdx.x];
        g_part_cnt[threadIdx.x * MAX_BLOCKS + blockIdx.x] = s_cnt[threadIdx.x];
    }

    // ---- last-block final reduction (fused tail) ----
    __threadfence();
    __syncthreads();
    __shared__ bool is_last;
    if (threadIdx.x == 0) {
        unsigned prev = atomicAdd(&g_done, 1u);
        is_last = (prev == gridDim.x - 1);
    }
    __syncthreads();

    if (is_last) {
        __shared__ double term[BINS];
        int w = threadIdx.x >> 5;
        for (int bin = w; bin < BINS; bin += NWARPS) {
            float    fs = 0.0f;
            unsigned fc = 0u;
            for (int blk = lane; blk < (int)gridDim.x; blk += 32) {
                fs += g_part_sum[bin * MAX_BLOCKS + blk];
                fc += g_part_cnt[bin * MAX_BLOCKS + blk];
            }
#pragma unroll
            for (int off = 16; off > 0; off >>= 1) {
                fs += __shfl_down_sync(0xFFFFFFFFu, fs, off);
                fc += __shfl_down_sync(0xFFFFFFFFu, fc, off);
            }
            if (lane == 0) {
                double c = (double)fc;
                if (c < 1.0) c = 1.0;
                term[bin] = ((double)N / (double)BINS) / c * (double)fs;
            }
        }
        __syncthreads();
        if (threadIdx.x == 0) {
            double total = 0.0;
#pragma unroll
            for (int b = 0; b < BINS; b++) total += term[b];
            out[0] = (float)total;
            g_done = 0;   // reset for next (graph-replayed) run
        }
    }
}

extern "C" void kernel_launch(void* const* d_in, const int* in_sizes, int n_in,
                              void* d_out, int out_size)
{
    // Robust input-order detection: inputs has 16x more elements than target.
    int i_x = 0, i_t = 1;
    if (n_in >= 2 && in_sizes[1] > in_sizes[0]) { i_x = 1; i_t = 0; }

    const float* x   = (const float*)d_in[i_x];
    const int*   tgt = (const int*)d_in[i_t];
    float*       out = (float*)d_out;

    int N = in_sizes[i_t];
    (void)out_size;

    long long witers = ((long long)N + 31) / 32;            // warp-iterations needed
    long long maxb = (witers + NWARPS - 1) / NWARPS;
    int blocks = MAX_BLOCKS;
    if ((long long)blocks > maxb) blocks = (int)maxb;
    if (blocks < 1) blocks = 1;

    ghm_fused_kernel<<<blocks, THREADS>>>(x, tgt, out, N);
}